// round 5
// baseline (speedup 1.0000x reference)
#include <cuda_runtime.h>
#include <cuda_bf16.h>
#include <cstdint>

// LinearRationalSpline forward — persistent TMA pipeline, ILP=2 per thread.
// inputs:  [16384, 64] f32     (N = 1048576)
// params:  [16384, 64, 63] f32 (w[16], h[16], d[15], lam[16])
// out:     [2*N] f32
//
// 6 blocks/SM, TPB=64, TILE=128 (each thread computes 2 elements -> two
// independent dependency chains hide MUFU/LDS latency). Double-buffered
// cp.async.bulk + mbarrier keeps DRAM streaming.

#define TPB   64
#define TILE  128
#define NBINS 16

#define STAGE_FLOATS (TILE * 63)
#define PARAMS_BYTES (STAGE_FLOATS * 4)          // 32256
#define X_BYTES      (TILE * 4)                  // 512
#define STAGE_BYTES  (PARAMS_BYTES + X_BYTES)    // 32768
#define BUF_OFF      64
#define SMEM_TOTAL   (BUF_OFF + 2 * STAGE_BYTES)

__device__ __forceinline__ uint32_t smem_u32(const void* p) {
    uint32_t a;
    asm("{ .reg .u64 t; cvta.to.shared.u64 t, %1; cvt.u32.u64 %0, t; }"
        : "=r"(a) : "l"(p));
    return a;
}
__device__ __forceinline__ void mbar_init(uint32_t mbar, uint32_t cnt) {
    asm volatile("mbarrier.init.shared.b64 [%0], %1;" :: "r"(mbar), "r"(cnt) : "memory");
}
__device__ __forceinline__ void mbar_expect_tx(uint32_t mbar, uint32_t bytes) {
    asm volatile("mbarrier.arrive.expect_tx.shared.b64 _, [%0], %1;"
                 :: "r"(mbar), "r"(bytes) : "memory");
}
__device__ __forceinline__ void mbar_wait(uint32_t mbar, uint32_t parity) {
    asm volatile(
        "{\n\t"
        ".reg .pred P1;\n\t"
        "WAIT_%=:\n\t"
        "mbarrier.try_wait.parity.acquire.cta.shared::cta.b64 P1, [%0], %1, 0x989680;\n\t"
        "@P1 bra.uni DONE_%=;\n\t"
        "bra.uni WAIT_%=;\n\t"
        "DONE_%=:\n\t"
        "}" :: "r"(mbar), "r"(parity) : "memory");
}
__device__ __forceinline__ void bulk_g2s(uint32_t dst, const void* src,
                                         uint32_t bytes, uint32_t mbar) {
    asm volatile(
        "cp.async.bulk.shared::cluster.global.mbarrier::complete_tx::bytes "
        "[%0], [%1], %2, [%3];"
        :: "r"(dst), "l"(src), "r"(bytes), "r"(mbar) : "memory");
}
__device__ __forceinline__ void fence_async() {
    asm volatile("fence.proxy.async.shared::cta;" ::: "memory");
}

__device__ __forceinline__ float softplus_f(float v) {
    return fmaxf(v, 0.0f) + __logf(1.0f + __expf(-fabsf(v)));
}

__device__ __forceinline__ void issue_tile(uint32_t sbase, int bsel,
                                           const float* params, const float* inputs,
                                           long long tile) {
    uint32_t mbar = sbase + bsel * 8;
    uint32_t dst  = sbase + BUF_OFF + bsel * STAGE_BYTES;
    mbar_expect_tx(mbar, STAGE_BYTES);
    bulk_g2s(dst, params + tile * STAGE_FLOATS, PARAMS_BYTES, mbar);
    bulk_g2s(dst + PARAMS_BYTES, inputs + tile * TILE, X_BYTES, mbar);
}

// one element's spline math (p = 63 params in smem, stride-63 conflict-free)
__device__ __forceinline__ void spline_one(const float* __restrict__ p, float x,
                                           float& outv, float& lad) {
    constexpr float BOUND = 3.0f;
    constexpr float MBW   = 0.001f;
    constexpr float MBH   = 0.001f;
    constexpr float MIND  = 0.001f;
    constexpr float MINL  = 0.025f;
    constexpr float EPSV  = 1e-6f;

    // widths / heights softmax cumsums (no max-subtract: |p| small)
    float cw[NBINS], ch[NBINS];
    {
        float s = 0.0f;
        #pragma unroll
        for (int i = 0; i < NBINS; i++) { s += __expf(p[i]); cw[i] = s; }
    }
    {
        float s = 0.0f;
        #pragma unroll
        for (int i = 0; i < NBINS; i++) { s += __expf(p[16 + i]); ch[i] = s; }
    }
    const float Aw = 6.0f * (1.0f - 16.0f * MBW) * __frcp_rn(cw[NBINS - 1]);
    const float Ah = 6.0f * (1.0f - 16.0f * MBH) * __frcp_rn(ch[NBINS - 1]);

    // fused bin search: width knot predicate also selects height knots
    int cnt = 0;
    float cumw  = -BOUND, wnext = BOUND;
    float ya    = -BOUND, ykn   = BOUND;
    bool found = false;
    #pragma unroll
    for (int i = 1; i <= 15; i++) {
        const float kv = fmaf(Aw, cw[i - 1], 6.0f * MBW * (float)i - BOUND);
        const float hv = fmaf(Ah, ch[i - 1], 6.0f * MBH * (float)i - BOUND);
        const bool c = (kv + EPSV) <= x;
        cnt  += c ? 1 : 0;
        cumw  = c ? kv : cumw;
        ya    = c ? hv : ya;
        if (!c && !found) { wnext = kv; ykn = hv; found = true; }
    }
    cnt += ((BOUND + EPSV) <= x) ? 1 : 0;
    const int b = cnt > 15 ? 15 : cnt;

    const float input_widths  = wnext - cumw;
    const float input_heights = ykn - ya;
    const float yb = input_heights + ya;

    // derivatives + lambda (dynamic LDS at stride-63 base)
    const float d0r  = p[32 + (b > 0  ? b - 1 : 0)];
    const float d1r  = p[32 + (b < 15 ? b     : 14)];
    const float lraw = p[47 + b];

    const float d0 = (b == 0)  ? (1.0f - MIND) : (MIND + softplus_f(d0r));
    const float d1 = (b == 15) ? (1.0f - MIND) : (MIND + softplus_f(d1r));

    const float sig = __frcp_rn(1.0f + __expf(-lraw));
    const float lam = fmaf(1.0f - 2.0f * MINL, sig, MINL);

    // rational spline
    const float wbv = __fsqrt_rn(__fdividef(d0, d1));
    const float lwb = lam * wbv;
    const float delta = __fdividef(input_heights, input_widths);
    const float wc = __fdividef(fmaf(lam, d0, (wbv - lwb) * d1), delta);
    const float l1 = 1.0f - lam;
    const float yc = __fdividef(lwb * yb + l1 * ya, l1 + lwb);

    const float theta = __fdividef(x - cumw, input_widths);
    const bool ind = theta <= lam;
    const float ltheta = lam - theta;

    const float wcyc = wc * yc;
    const float wcyctheta = wcyc * theta;
    const float num = ind ? fmaf(ya, ltheta, wcyctheta)
                          : (wcyc - wcyctheta) - (wbv * yb) * ltheta;
    const float wctheta = wc * theta;
    const float den = ind ? (wctheta + ltheta)
                          : (wc - wctheta) - wbv * ltheta;
    outv = __fdividef(num, den);

    // logabsdet = log(dnum) - 2 log|den| = log( wc*sel / (w * den^2) )
    const float sel = ind ? lam * (yc - ya) : (wbv - lwb) * (yb - yc);
    lad = __logf(__fdividef(wc * sel, input_widths * (den * den)));
}

__global__ __launch_bounds__(TPB)
void lrs_kernel(const float* __restrict__ inputs,
                const float* __restrict__ params,
                float* __restrict__ out,
                int N, int numTiles)
{
    constexpr float BOUND = 3.0f;

    extern __shared__ char smem[];
    const uint32_t sbase = smem_u32(smem);
    const int tid = threadIdx.x;

    if (tid == 0) {
        mbar_init(sbase + 0, 1);
        mbar_init(sbase + 8, 1);
        fence_async();
    }
    __syncthreads();

    const long long step = gridDim.x;

    if (tid == 0) {
        long long t0 = blockIdx.x;
        long long t1 = blockIdx.x + step;
        if (t0 < numTiles && (t0 + 1) * TILE <= N)
            issue_tile(sbase, 0, params, inputs, t0);
        if (t1 < numTiles && (t1 + 1) * TILE <= N)
            issue_tile(sbase, 1, params, inputs, t1);
    }

    int phase0 = 0, phase1 = 0;
    int bsel = 0;

    for (long long tile = blockIdx.x; tile < numTiles; tile += step) {
        const long long e0 = tile * TILE;
        const int elems = (N - e0) < TILE ? (int)(N - e0) : TILE;
        float* bufp = (float*)(smem + BUF_OFF + bsel * STAGE_BYTES);
        float* bufx = bufp + STAGE_FLOATS;

        if (elems == TILE) {
            if (bsel == 0) { mbar_wait(sbase + 0, phase0); phase0 ^= 1; }
            else           { mbar_wait(sbase + 8, phase1); phase1 ^= 1; }
        } else {
            for (int i = tid; i < elems * 63; i += TPB)
                bufp[i] = params[e0 * 63 + i];
            for (int i = tid; i < elems; i += TPB)
                bufx[i] = inputs[e0 + i];
            __syncthreads();
        }

        // element A: tid,  element B: tid + 64  (two independent chains)
        const bool doA = tid < elems;
        const bool doB = (tid + TPB) < elems;

        float xA = 0.0f, xB = 0.0f;
        float oA = 0.0f, lA = 0.0f, oB = 0.0f, lB = 0.0f;
        if (doA) xA = bufx[tid];
        if (doB) xB = bufx[tid + TPB];

        if (doA && doB) {
            spline_one(bufp + tid * 63, xA, oA, lA);
            spline_one(bufp + (tid + TPB) * 63, xB, oB, lB);
        } else if (doA) {
            spline_one(bufp + tid * 63, xA, oA, lA);
        }

        if (doA) {
            const bool outside = (xA < -BOUND) || (xA > BOUND);
            const int e = (int)e0 + tid;
            out[e]     = outside ? xA   : oA;
            out[N + e] = outside ? 0.0f : lA;
        }
        if (doB) {
            const bool outside = (xB < -BOUND) || (xB > BOUND);
            const int e = (int)e0 + tid + TPB;
            out[e]     = outside ? xB   : oB;
            out[N + e] = outside ? 0.0f : lB;
        }

        __syncthreads();   // everyone done reading this buffer

        long long nt = tile + 2 * step;
        if (tid == 0 && nt < numTiles && (nt + 1) * TILE <= N) {
            fence_async();
            issue_tile(sbase, bsel, params, inputs, nt);
        }
        bsel ^= 1;
    }
}

extern "C" void kernel_launch(void* const* d_in, const int* in_sizes, int n_in,
                              void* d_out, int out_size) {
    const float* inputs = (const float*)d_in[0];
    const float* params = (const float*)d_in[1];
    float* out = (float*)d_out;
    const int N = in_sizes[0];
    const int numTiles = (N + TILE - 1) / TILE;

    cudaFuncSetAttribute(lrs_kernel,
                         cudaFuncAttributeMaxDynamicSharedMemorySize, SMEM_TOTAL);

    int grid = 148 * 6;                    // persistent: 6 blocks/SM
    if (grid > numTiles) grid = numTiles;
    lrs_kernel<<<grid, TPB, SMEM_TOTAL>>>(inputs, params, out, N, numTiles);
}

// round 6
// speedup vs baseline: 1.0766x; 1.0766x over previous
#include <cuda_runtime.h>
#include <cuda_bf16.h>
#include <cstdint>

// LinearRationalSpline forward — persistent TMA pipeline, fine-grained tiles.
// inputs:  [16384, 64] f32     (N = 1048576)
// params:  [16384, 64, 63] f32 (w[16], h[16], d[15], lam[16])
// out:     [2*N] f32
//
// TILE=64, TPB=64, double-buffered cp.async.bulk (16.1 KB params + 256 B x
// per tile) -> 32.8 KB smem/block -> 6 resident blocks/SM (12 warps/SM,
// 6 independent pipeline streams). Grid sized to exactly one wave.

#define TPB   64
#define TILE  64
#define NBINS 16
#define BLOCKS_PER_SM 6
#define NUM_SMS 148

#define STAGE_FLOATS (TILE * 63)
#define PARAMS_BYTES (STAGE_FLOATS * 4)          // 16128
#define X_BYTES      (TILE * 4)                  // 256
#define STAGE_BYTES  (PARAMS_BYTES + X_BYTES)    // 16384
#define BUF_OFF      64
#define SMEM_TOTAL   (BUF_OFF + 2 * STAGE_BYTES) // 32832

__device__ __forceinline__ uint32_t smem_u32(const void* p) {
    uint32_t a;
    asm("{ .reg .u64 t; cvta.to.shared.u64 t, %1; cvt.u32.u64 %0, t; }"
        : "=r"(a) : "l"(p));
    return a;
}
__device__ __forceinline__ void mbar_init(uint32_t mbar, uint32_t cnt) {
    asm volatile("mbarrier.init.shared.b64 [%0], %1;" :: "r"(mbar), "r"(cnt) : "memory");
}
__device__ __forceinline__ void mbar_expect_tx(uint32_t mbar, uint32_t bytes) {
    asm volatile("mbarrier.arrive.expect_tx.shared.b64 _, [%0], %1;"
                 :: "r"(mbar), "r"(bytes) : "memory");
}
__device__ __forceinline__ void mbar_wait(uint32_t mbar, uint32_t parity) {
    asm volatile(
        "{\n\t"
        ".reg .pred P1;\n\t"
        "WAIT_%=:\n\t"
        "mbarrier.try_wait.parity.acquire.cta.shared::cta.b64 P1, [%0], %1, 0x989680;\n\t"
        "@P1 bra.uni DONE_%=;\n\t"
        "bra.uni WAIT_%=;\n\t"
        "DONE_%=:\n\t"
        "}" :: "r"(mbar), "r"(parity) : "memory");
}
__device__ __forceinline__ void bulk_g2s(uint32_t dst, const void* src,
                                         uint32_t bytes, uint32_t mbar) {
    asm volatile(
        "cp.async.bulk.shared::cluster.global.mbarrier::complete_tx::bytes "
        "[%0], [%1], %2, [%3];"
        :: "r"(dst), "l"(src), "r"(bytes), "r"(mbar) : "memory");
}
__device__ __forceinline__ void fence_async() {
    asm volatile("fence.proxy.async.shared::cta;" ::: "memory");
}

__device__ __forceinline__ float softplus_f(float v) {
    return fmaxf(v, 0.0f) + __logf(1.0f + __expf(-fabsf(v)));
}

__device__ __forceinline__ void issue_tile(uint32_t sbase, int bsel,
                                           const float* params, const float* inputs,
                                           long long tile) {
    uint32_t mbar = sbase + bsel * 8;
    uint32_t dst  = sbase + BUF_OFF + bsel * STAGE_BYTES;
    mbar_expect_tx(mbar, STAGE_BYTES);
    bulk_g2s(dst, params + tile * STAGE_FLOATS, PARAMS_BYTES, mbar);
    bulk_g2s(dst + PARAMS_BYTES, inputs + tile * TILE, X_BYTES, mbar);
}

// one element's spline math (p = 63 params in smem, stride-63 conflict-free)
__device__ __forceinline__ void spline_one(const float* __restrict__ p, float x,
                                           float& outv, float& lad) {
    constexpr float BOUND = 3.0f;
    constexpr float MBW   = 0.001f;
    constexpr float MBH   = 0.001f;
    constexpr float MIND  = 0.001f;
    constexpr float MINL  = 0.025f;
    constexpr float EPSV  = 1e-6f;

    // widths / heights softmax cumsums (no max-subtract: |p| small, f32 safe)
    float cw[NBINS], ch[NBINS];
    {
        float s = 0.0f;
        #pragma unroll
        for (int i = 0; i < NBINS; i++) { s += __expf(p[i]); cw[i] = s; }
    }
    {
        float s = 0.0f;
        #pragma unroll
        for (int i = 0; i < NBINS; i++) { s += __expf(p[16 + i]); ch[i] = s; }
    }
    const float Aw = 6.0f * (1.0f - 16.0f * MBW) * __frcp_rn(cw[NBINS - 1]);
    const float Ah = 6.0f * (1.0f - 16.0f * MBH) * __frcp_rn(ch[NBINS - 1]);

    // fused bin search: width knot predicate also selects height knots
    int cnt = 0;
    float cumw  = -BOUND, wnext = BOUND;
    float ya    = -BOUND, ykn   = BOUND;
    bool found = false;
    #pragma unroll
    for (int i = 1; i <= 15; i++) {
        const float kv = fmaf(Aw, cw[i - 1], 6.0f * MBW * (float)i - BOUND);
        const float hv = fmaf(Ah, ch[i - 1], 6.0f * MBH * (float)i - BOUND);
        const bool c = (kv + EPSV) <= x;
        cnt  += c ? 1 : 0;
        cumw  = c ? kv : cumw;
        ya    = c ? hv : ya;
        if (!c && !found) { wnext = kv; ykn = hv; found = true; }
    }
    cnt += ((BOUND + EPSV) <= x) ? 1 : 0;
    const int b = cnt > 15 ? 15 : cnt;

    const float input_widths  = wnext - cumw;
    const float input_heights = ykn - ya;
    const float yb = input_heights + ya;

    // derivatives + lambda (dynamic LDS)
    const float d0r  = p[32 + (b > 0  ? b - 1 : 0)];
    const float d1r  = p[32 + (b < 15 ? b     : 14)];
    const float lraw = p[47 + b];

    const float d0 = (b == 0)  ? (1.0f - MIND) : (MIND + softplus_f(d0r));
    const float d1 = (b == 15) ? (1.0f - MIND) : (MIND + softplus_f(d1r));

    const float sig = __frcp_rn(1.0f + __expf(-lraw));
    const float lam = fmaf(1.0f - 2.0f * MINL, sig, MINL);

    // rational spline
    const float wbv = __fsqrt_rn(__fdividef(d0, d1));
    const float lwb = lam * wbv;
    const float delta = __fdividef(input_heights, input_widths);
    const float wc = __fdividef(fmaf(lam, d0, (wbv - lwb) * d1), delta);
    const float l1 = 1.0f - lam;
    const float yc = __fdividef(lwb * yb + l1 * ya, l1 + lwb);

    const float theta = __fdividef(x - cumw, input_widths);
    const bool ind = theta <= lam;
    const float ltheta = lam - theta;

    const float wcyc = wc * yc;
    const float wcyctheta = wcyc * theta;
    const float num = ind ? fmaf(ya, ltheta, wcyctheta)
                          : (wcyc - wcyctheta) - (wbv * yb) * ltheta;
    const float wctheta = wc * theta;
    const float den = ind ? (wctheta + ltheta)
                          : (wc - wctheta) - wbv * ltheta;
    outv = __fdividef(num, den);

    // logabsdet = log( wc*sel / (w * den^2) )
    const float sel = ind ? lam * (yc - ya) : (wbv - lwb) * (yb - yc);
    lad = __logf(__fdividef(wc * sel, input_widths * (den * den)));
}

__global__ __launch_bounds__(TPB)
void lrs_kernel(const float* __restrict__ inputs,
                const float* __restrict__ params,
                float* __restrict__ out,
                int N, int numTiles)
{
    constexpr float BOUND = 3.0f;

    extern __shared__ char smem[];
    const uint32_t sbase = smem_u32(smem);
    const int tid = threadIdx.x;

    if (tid == 0) {
        mbar_init(sbase + 0, 1);
        mbar_init(sbase + 8, 1);
        fence_async();
    }
    __syncthreads();

    const long long step = gridDim.x;

    if (tid == 0) {
        long long t0 = blockIdx.x;
        long long t1 = blockIdx.x + step;
        if (t0 < numTiles && (t0 + 1) * TILE <= N)
            issue_tile(sbase, 0, params, inputs, t0);
        if (t1 < numTiles && (t1 + 1) * TILE <= N)
            issue_tile(sbase, 1, params, inputs, t1);
    }

    int phase0 = 0, phase1 = 0;
    int bsel = 0;

    for (long long tile = blockIdx.x; tile < numTiles; tile += step) {
        const long long e0 = tile * TILE;
        const int elems = (N - e0) < TILE ? (int)(N - e0) : TILE;
        float* bufp = (float*)(smem + BUF_OFF + bsel * STAGE_BYTES);
        float* bufx = bufp + STAGE_FLOATS;

        if (elems == TILE) {
            if (bsel == 0) { mbar_wait(sbase + 0, phase0); phase0 ^= 1; }
            else           { mbar_wait(sbase + 8, phase1); phase1 ^= 1; }
        } else {
            // partial tail tile (not hit for N % 64 == 0)
            for (int i = tid; i < elems * 63; i += TPB)
                bufp[i] = params[e0 * 63 + i];
            for (int i = tid; i < elems; i += TPB)
                bufx[i] = inputs[e0 + i];
            __syncthreads();
        }

        if (tid < elems) {
            const float x = bufx[tid];
            float outv, lad;
            spline_one(bufp + tid * 63, x, outv, lad);

            const bool outside = (x < -BOUND) || (x > BOUND);
            const int e = (int)e0 + tid;
            out[e]     = outside ? x    : outv;
            out[N + e] = outside ? 0.0f : lad;
        }

        __syncthreads();   // all warps done reading this buffer

        long long nt = tile + 2 * step;
        if (tid == 0 && nt < numTiles && (nt + 1) * TILE <= N) {
            fence_async();
            issue_tile(sbase, bsel, params, inputs, nt);
        }
        bsel ^= 1;
    }
}

extern "C" void kernel_launch(void* const* d_in, const int* in_sizes, int n_in,
                              void* d_out, int out_size) {
    const float* inputs = (const float*)d_in[0];
    const float* params = (const float*)d_in[1];
    float* out = (float*)d_out;
    const int N = in_sizes[0];
    const int numTiles = (N + TILE - 1) / TILE;

    cudaFuncSetAttribute(lrs_kernel,
                         cudaFuncAttributeMaxDynamicSharedMemorySize, SMEM_TOTAL);

    int grid = NUM_SMS * BLOCKS_PER_SM;    // exactly one resident wave
    if (grid > numTiles) grid = numTiles;
    lrs_kernel<<<grid, TPB, SMEM_TOTAL>>>(inputs, params, out, N, numTiles);
}